// round 2
// baseline (speedup 1.0000x reference)
#include <cuda_runtime.h>

#define NN 20000
#define EE 400000
#define CC 16
#define NSH 9
#define HH 64
#define NB 8
#define NL 3
#define TABN 4096
#define RMIN 0.5f
#define RCUT 5.0f
#define ROWF (CC*NSH)          // 144 floats per node
#define XSZ (NN*ROWF)

__device__ float g_x[XSZ];
__device__ float g_agg[XSZ];
__device__ float g_Rtab[NL*TABN*32];

__device__ __forceinline__ float sspf(float v) {
    // softplus(v) - ln2, numerically stable
    return fmaxf(v, 0.f) + log1pf(__expf(-fabsf(v))) - 0.69314718055994531f;
}

__device__ __forceinline__ void red4(float* p, float4 v) {
    asm volatile("red.global.add.v4.f32 [%0], {%1, %2, %3, %4};"
                 :: "l"(p), "f"(v.x), "f"(v.y), "f"(v.z), "f"(v.w) : "memory");
}

// ---------------------------------------------------------------------------
// Build per-layer radial tables: R(r) = ssp(ebasis(r) @ W1) @ W2 * deg_norm
// ---------------------------------------------------------------------------
__global__ void build_tables(const float* __restrict__ W1,
                             const float* __restrict__ W2) {
    int idx = blockIdx.x * blockDim.x + threadIdx.x;
    if (idx >= NL * TABN) return;
    int layer = idx / TABN;
    int k     = idx % TABN;
    float r = RMIN + (RCUT - RMIN) * ((float)k / (float)(TABN - 1));
    float u = r / RCUT;
    float u3 = u * u * u;
    float u6 = u3 * u3;
    float env = 1.f - 28.f * u6 + 48.f * u6 * u - 21.f * u6 * u * u;
    if (k == TABN - 1) env = 0.f;   // exact zero at cutoff
    float pref = sqrtf(2.f / RCUT) / r * env;
    float eb[NB];
#pragma unroll
    for (int n = 0; n < NB; n++)
        eb[n] = pref * sinf((float)(n + 1) * 3.14159265358979323846f * r / RCUT);

    const float* w1 = W1 + (size_t)layer * NB * HH;
    const float* w2 = W2 + (size_t)layer * HH * (2 * CC);
    float Racc[32];
#pragma unroll
    for (int c = 0; c < 32; c++) Racc[c] = 0.f;
    for (int j = 0; j < HH; j++) {
        float h = 0.f;
#pragma unroll
        for (int n = 0; n < NB; n++) h += eb[n] * w1[n * HH + j];
        float a = sspf(h);
#pragma unroll
        for (int c = 0; c < 32; c++) Racc[c] += a * w2[j * 32 + c];
    }
    const float deg_norm = 0.22360679774997896f;  // 1/sqrt(E/N) = 1/sqrt(20)
    float* dst = g_Rtab + ((size_t)layer * TABN + k) * 32;
#pragma unroll
    for (int c = 0; c < 32; c++) dst[c] = Racc[c] * deg_norm;
}

// ---------------------------------------------------------------------------
// x[n][m][c]: m=0 row = W_embed[species], rest 0
// ---------------------------------------------------------------------------
__global__ void init_x(const int* __restrict__ species,
                       const float* __restrict__ Wemb) {
    int idx = blockIdx.x * blockDim.x + threadIdx.x;
    if (idx >= XSZ) return;
    int n   = idx / ROWF;
    int rem = idx % ROWF;
    int m = rem / CC, c = rem % CC;
    g_x[idx] = (m == 0) ? Wemb[species[n] * CC + c] : 0.f;
}

__global__ void zero_agg() {
    for (int idx = blockIdx.x * blockDim.x + threadIdx.x; idx < XSZ / 4;
         idx += gridDim.x * blockDim.x)
        ((float4*)g_agg)[idx] = make_float4(0.f, 0.f, 0.f, 0.f);
}

// ---------------------------------------------------------------------------
// Edge kernel: lerp R from table, compute Y, gather x[src], scatter to agg[dst]
// ---------------------------------------------------------------------------
__global__ void __launch_bounds__(256)
edge_kernel(const int* __restrict__ eidx, const float* __restrict__ diff,
            const float* __restrict__ dist, int layer) {
    int e = blockIdx.x * blockDim.x + threadIdx.x;
    if (e >= EE) return;
    float r = dist[e];
    if (!(r < RCUT)) return;            // mask: msg would be zero
    int src = eidx[2 * e];
    int dst = eidx[2 * e + 1];

    // radial table lerp (32 values); next row starts 8 float4s later
    float t = (r - RMIN) * ((float)(TABN - 1) / (RCUT - RMIN));
    t = fminf(fmaxf(t, 0.f), (float)(TABN - 1) - 1e-3f);
    int k0 = (int)t;
    float f = t - (float)k0;
    const float4* A = (const float4*)(g_Rtab + ((size_t)layer * TABN + k0) * 32);
    float4 R[8];
#pragma unroll
    for (int v = 0; v < 8; v++) {
        float4 a = A[v], b = A[v + 8];
        R[v].x = a.x + f * (b.x - a.x);
        R[v].y = a.y + f * (b.y - a.y);
        R[v].z = a.z + f * (b.z - a.z);
        R[v].w = a.w + f * (b.w - a.w);
    }

    // spherical harmonics (l=0,1,2)
    float dx = diff[3 * e], dy = diff[3 * e + 1], dz = diff[3 * e + 2];
    float inv = rsqrtf(dx * dx + dy * dy + dz * dz);
    float ux = dx * inv, uy = dy * inv, uz = dz * inv;
    const float s3 = 1.7320508075688772f;
    const float s5 = 2.2360679774997896f;
    const float s15 = 3.8729833462074170f;
    float Y[9];
    Y[0] = 1.f;
    Y[1] = s3 * ux; Y[2] = s3 * uy; Y[3] = s3 * uz;
    Y[4] = s15 * ux * uy;
    Y[5] = s15 * uy * uz;
    Y[6] = 0.5f * s5 * (2.f * uz * uz - ux * ux - uy * uy);
    Y[7] = s15 * ux * uz;
    Y[8] = 0.5f * s15 * (ux * ux - uy * uy);

    const float4* xs = (const float4*)(g_x + (size_t)src * ROWF);
    float4 x0[4];
#pragma unroll
    for (int v = 0; v < 4; v++) x0[v] = xs[v];

    float* aggbase = g_agg + (size_t)dst * ROWF;
#pragma unroll
    for (int m = 0; m < 9; m++) {
        float ym = Y[m];
#pragma unroll
        for (int v = 0; v < 4; v++) {
            float4 xm = (m == 0) ? x0[v] : xs[m * 4 + v];
            float4 r1 = R[v], r2 = R[4 + v];
            float4 msg;
            msg.x = r1.x * x0[v].x * ym + r2.x * xm.x;
            msg.y = r1.y * x0[v].y * ym + r2.y * xm.y;
            msg.z = r1.z * x0[v].z * ym + r2.z * xm.z;
            msg.w = r1.w * x0[v].w * ym + r2.w * xm.w;
            red4(aggbase + m * CC + v * 4, msg);
        }
    }
}

// ---------------------------------------------------------------------------
// Node kernel: mix per l-group, gate, write new x
// ---------------------------------------------------------------------------
__global__ void __launch_bounds__(128)
node_kernel(const float* __restrict__ Wmix, const float* __restrict__ Wg,
            int layer) {
    __shared__ float sWm[3 * CC * CC];   // 768
    __shared__ float sWg[CC * 2 * CC];   // 512
    for (int i = threadIdx.x; i < 3 * CC * CC; i += blockDim.x)
        sWm[i] = Wmix[(size_t)layer * 3 * CC * CC + i];
    for (int i = threadIdx.x; i < CC * 2 * CC; i += blockDim.x)
        sWg[i] = Wg[(size_t)layer * CC * 2 * CC + i];
    __syncthreads();

    int n = blockIdx.x * blockDim.x + threadIdx.x;
    if (n >= NN) return;
    const float* ag = g_agg + (size_t)n * ROWF;
    float* xo = g_x + (size_t)n * ROWF;

    // m = 0: s = agg[0] @ Wmix0
    float a[16], s[16];
#pragma unroll
    for (int c = 0; c < 16; c++) a[c] = ag[c];
#pragma unroll
    for (int d = 0; d < 16; d++) {
        float acc = 0.f;
#pragma unroll
        for (int c = 0; c < 16; c++) acc += a[c] * sWm[c * 16 + d];
        s[d] = acc;
    }
    // gate
    float g[32];
#pragma unroll
    for (int j = 0; j < 32; j++) {
        float acc = 0.f;
#pragma unroll
        for (int c = 0; c < 16; c++) acc += s[c] * sWg[c * 32 + j];
        g[j] = 1.f / (1.f + __expf(-acc));
    }
#pragma unroll
    for (int d = 0; d < 16; d++) xo[d] = sspf(s[d]);

#pragma unroll
    for (int m = 1; m < 9; m++) {
        const float* wm = sWm + ((m < 4) ? 1 : 2) * 256;
#pragma unroll
        for (int c = 0; c < 16; c++) a[c] = ag[m * CC + c];
#pragma unroll
        for (int d = 0; d < 16; d++) {
            float acc = 0.f;
#pragma unroll
            for (int c = 0; c < 16; c++) acc += a[c] * wm[c * 16 + d];
            float gv = (m < 4) ? g[d] : g[16 + d];
            xo[m * CC + d] = acc * gv;
        }
    }
}

// ---------------------------------------------------------------------------
// Readout: out[n] = ssp(x[n,0,:] @ Wr1) @ wr2
// ---------------------------------------------------------------------------
__global__ void __launch_bounds__(128)
final_kernel(const float* __restrict__ Wr1, const float* __restrict__ wr2,
             float* __restrict__ out) {
    __shared__ float sW[CC * HH];   // 1024
    __shared__ float sw2[HH];
    for (int i = threadIdx.x; i < CC * HH; i += blockDim.x) sW[i] = Wr1[i];
    for (int i = threadIdx.x; i < HH; i += blockDim.x) sw2[i] = wr2[i];
    __syncthreads();

    int n = blockIdx.x * blockDim.x + threadIdx.x;
    if (n >= NN) return;
    float v[16];
    const float* xp = g_x + (size_t)n * ROWF;
#pragma unroll
    for (int c = 0; c < 16; c++) v[c] = xp[c];
    float acc = 0.f;
#pragma unroll
    for (int j = 0; j < HH; j++) {
        float h = 0.f;
#pragma unroll
        for (int c = 0; c < 16; c++) h += v[c] * sW[c * HH + j];
        acc += sspf(h) * sw2[j];
    }
    out[n] = acc;
}

// ---------------------------------------------------------------------------
extern "C" void kernel_launch(void* const* d_in, const int* in_sizes, int n_in,
                              void* d_out, int out_size) {
    const int*   species = (const int*)d_in[0];
    const int*   eidx    = (const int*)d_in[1];
    const float* diff    = (const float*)d_in[2];
    const float* dist    = (const float*)d_in[3];
    const float* Wemb    = (const float*)d_in[4];
    const float* W1      = (const float*)d_in[5];
    const float* W2      = (const float*)d_in[6];
    const float* Wmix    = (const float*)d_in[7];
    const float* Wg      = (const float*)d_in[8];
    const float* Wr1     = (const float*)d_in[9];
    const float* wr2     = (const float*)d_in[10];
    float* out = (float*)d_out;

    build_tables<<<(NL * TABN + 127) / 128, 128>>>(W1, W2);
    init_x<<<(XSZ + 255) / 256, 256>>>(species, Wemb);
    for (int layer = 0; layer < NL; layer++) {
        zero_agg<<<(XSZ / 4 + 255) / 256, 256>>>();
        edge_kernel<<<(EE + 255) / 256, 256>>>(eidx, diff, dist, layer);
        node_kernel<<<(NN + 127) / 128, 128>>>(Wmix, Wg, layer);
    }
    final_kernel<<<(NN + 127) / 128, 128>>>(Wr1, wr2, out);
}

// round 3
// speedup vs baseline: 3.8720x; 3.8720x over previous
#include <cuda_runtime.h>

#define NN 20000
#define EE 400000
#define CC 16
#define NSH 9
#define HH 64
#define NB 8
#define NL 3
#define TABN 4096
#define SLOTS 64
#define RMIN 0.5f
#define RCUT 5.0f
#define ROWF (CC*NSH)          // 144 floats per node
#define XSZ (NN*ROWF)

__device__ float  g_xbuf[2 * XSZ];
__device__ float  g_Rtab[NL * TABN * 32];
__device__ int    g_cnt[NN];
__device__ float4 g_rec[(size_t)NN * SLOTS * 3];   // 48B per edge record

__device__ __forceinline__ float sspf(float v) {
    return fmaxf(v, 0.f) + log1pf(__expf(-fabsf(v))) - 0.69314718055994531f;
}

// ---------------------------------------------------------------------------
// Radial tables: R(r) = ssp(ebasis(r) @ W1) @ W2 * deg_norm, 32 values per knot
// ---------------------------------------------------------------------------
__global__ void build_tables(const float* __restrict__ W1,
                             const float* __restrict__ W2) {
    int idx = blockIdx.x * blockDim.x + threadIdx.x;
    if (idx >= NL * TABN) return;
    int layer = idx / TABN;
    int k     = idx % TABN;
    float r = RMIN + (RCUT - RMIN) * ((float)k / (float)(TABN - 1));
    float u = r / RCUT;
    float u3 = u * u * u;
    float u6 = u3 * u3;
    float env = 1.f - 28.f * u6 + 48.f * u6 * u - 21.f * u6 * u * u;
    if (k == TABN - 1) env = 0.f;
    float pref = sqrtf(2.f / RCUT) / r * env;
    float eb[NB];
#pragma unroll
    for (int n = 0; n < NB; n++)
        eb[n] = pref * sinf((float)(n + 1) * 3.14159265358979323846f * r / RCUT);

    const float* w1 = W1 + (size_t)layer * NB * HH;
    const float* w2 = W2 + (size_t)layer * HH * (2 * CC);
    float Racc[32];
#pragma unroll
    for (int c = 0; c < 32; c++) Racc[c] = 0.f;
    for (int j = 0; j < HH; j++) {
        float h = 0.f;
#pragma unroll
        for (int n = 0; n < NB; n++) h += eb[n] * w1[n * HH + j];
        float a = sspf(h);
#pragma unroll
        for (int c = 0; c < 32; c++) Racc[c] += a * w2[j * 32 + c];
    }
    const float deg_norm = 0.22360679774997896f;  // 1/sqrt(20)
    float* dst = g_Rtab + ((size_t)layer * TABN + k) * 32;
#pragma unroll
    for (int c = 0; c < 32; c++) dst[c] = Racc[c] * deg_norm;
}

// ---------------------------------------------------------------------------
__global__ void zero_cnt() {
    int i = blockIdx.x * blockDim.x + threadIdx.x;
    if (i < NN) g_cnt[i] = 0;
}

// x buffer 0: m=0 row = W_embed[species], rest 0
__global__ void init_x(const int* __restrict__ species,
                       const float* __restrict__ Wemb) {
    int idx = blockIdx.x * blockDim.x + threadIdx.x;
    if (idx >= XSZ) return;
    int n   = idx / ROWF;
    int rem = idx % ROWF;
    g_xbuf[idx] = (rem < CC) ? Wemb[species[n] * CC + rem] : 0.f;
}

// ---------------------------------------------------------------------------
// Build slotted CSR: per-edge record {src, t, Y1..Y8} at dst's next slot.
// ---------------------------------------------------------------------------
__global__ void __launch_bounds__(256)
build_edges(const int* __restrict__ eidx, const float* __restrict__ diff,
            const float* __restrict__ dist) {
    int e = blockIdx.x * blockDim.x + threadIdx.x;
    if (e >= EE) return;
    float r = dist[e];
    if (!(r < RCUT)) return;
    int src = eidx[2 * e];
    int dst = eidx[2 * e + 1];
    int pos = atomicAdd(&g_cnt[dst], 1);
    if (pos >= SLOTS) return;   // statistically unreachable

    float dx = diff[3 * e], dy = diff[3 * e + 1], dz = diff[3 * e + 2];
    float inv = rsqrtf(dx * dx + dy * dy + dz * dz);
    float ux = dx * inv, uy = dy * inv, uz = dz * inv;
    const float s3 = 1.7320508075688772f;
    const float s5 = 2.2360679774997896f;
    const float s15 = 3.8729833462074170f;
    float Y1 = s3 * ux, Y2 = s3 * uy, Y3 = s3 * uz;
    float Y4 = s15 * ux * uy;
    float Y5 = s15 * uy * uz;
    float Y6 = 0.5f * s5 * (2.f * uz * uz - ux * ux - uy * uy);
    float Y7 = s15 * ux * uz;
    float Y8 = 0.5f * s15 * (ux * ux - uy * uy);

    float t = (r - RMIN) * ((float)(TABN - 1) / (RCUT - RMIN));
    t = fminf(fmaxf(t, 0.f), (float)(TABN - 1) - 1e-3f);

    float4* rec = g_rec + ((size_t)dst * SLOTS + pos) * 3;
    rec[0] = make_float4(__int_as_float(src), t, Y1, Y2);
    rec[1] = make_float4(Y3, Y4, Y5, Y6);
    rec[2] = make_float4(Y7, Y8, 0.f, 0.f);
}

// ---------------------------------------------------------------------------
// Fused layer: warp per node. Aggregate over CSR edges (no atomics), then
// mix (Wmix), gate (Wg), activate, write new x coalesced.
// Lane layout: half0 (lanes 0-15): m=0..4 at c=lane; half1: m=5..8 at c=lane-16.
// ---------------------------------------------------------------------------
__global__ void __launch_bounds__(256)
layer_kernel(int layer, int rd,
             const float* __restrict__ Wmix, const float* __restrict__ Wg) {
    __shared__ float sWm[3 * CC * CC];   // 768
    __shared__ float sWg[CC * 2 * CC];   // 512
    for (int i = threadIdx.x; i < 768; i += 256)
        sWm[i] = Wmix[layer * 768 + i];
    for (int i = threadIdx.x; i < 512; i += 256)
        sWg[i] = Wg[layer * 512 + i];
    __syncthreads();

    int n = blockIdx.x * 8 + (threadIdx.x >> 5);
    if (n >= NN) return;
    int lane = threadIdx.x & 31;
    int half = lane >> 4;
    int c    = lane & 15;
    const unsigned FULL = 0xffffffffu;

    const float* xin  = g_xbuf + (size_t)rd * XSZ;
    float*       xout = g_xbuf + (size_t)(1 - rd) * XSZ;
    const float* tab  = g_Rtab + (size_t)layer * TABN * 32;

    int cnt = min(g_cnt[n], SLOTS);
    const float4* recbase = g_rec + (size_t)n * SLOTS * 3;
    int xoff = half * 80 + c;

    float a0 = 0.f, a1 = 0.f, a2 = 0.f, a3 = 0.f, a4 = 0.f;

    for (int e = 0; e < cnt; e++) {
        float4 r0 = recbase[e * 3];
        float4 r1 = recbase[e * 3 + 1];
        float4 r2 = recbase[e * 3 + 2];
        int   src = __float_as_int(r0.x);
        float t   = r0.y;
        int   k0  = (int)t;
        float f   = t - (float)k0;
        const float* T0 = tab + k0 * 32;
        float R1 = fmaf(f, T0[32 + c] - T0[c],       T0[c]);
        float R2 = fmaf(f, T0[48 + c] - T0[16 + c],  T0[16 + c]);

        const float* xb = xin + (size_t)src * ROWF;
        float xa = xb[xoff];
        float xv1 = xb[xoff + 16];
        float xv2 = xb[xoff + 32];
        float xv3 = xb[xoff + 48];
        float xv4 = xb[c + 64];          // only meaningful for half0 (m=4)
        float x0 = __shfl_sync(FULL, xa, c);   // x[src][0][c] lives in half0 lane c

        float Ya = half ? r1.z : 1.f;    // m=5 : m=0
        float Yb = half ? r1.w : r0.z;   // m=6 : m=1
        float Yc = half ? r2.x : r0.w;   // m=7 : m=2
        float Yd = half ? r2.y : r1.x;   // m=8 : m=3
        float Ye = r1.y;                 // m=4 (half0 only)

        float p = R1 * x0;
        a0 = fmaf(p, Ya, fmaf(R2, xa,  a0));
        a1 = fmaf(p, Yb, fmaf(R2, xv1, a1));
        a2 = fmaf(p, Yc, fmaf(R2, xv2, a2));
        a3 = fmaf(p, Yd, fmaf(R2, xv3, a3));
        if (!half) a4 = fmaf(p, Ye, fmaf(R2, xv4, a4));
    }

    // ---- mix: out[m][d] = sum_c agg[m][c] * W[c][d] (per l-group weights)
    const float* WA = half ? sWm + 512 : sWm;        // m=5 : m=0
    const float* WB = half ? sWm + 512 : sWm + 256;  // m=6 : m=1
    const float* WC = half ? sWm + 512 : sWm + 256;  // m=7 : m=2
    const float* WD = half ? sWm + 512 : sWm + 256;  // m=8 : m=3
    const float* WE = sWm + 512;                     // m=4
    int sbase = half << 4;
    float oA = 0.f, oB = 0.f, oC = 0.f, oD = 0.f, oE = 0.f;
#pragma unroll
    for (int cc = 0; cc < 16; cc++) {
        float vA = __shfl_sync(FULL, a0, sbase + cc);
        float vB = __shfl_sync(FULL, a1, sbase + cc);
        float vC = __shfl_sync(FULL, a2, sbase + cc);
        float vD = __shfl_sync(FULL, a3, sbase + cc);
        float vE = __shfl_sync(FULL, a4, sbase + cc);
        oA = fmaf(vA, WA[cc * 16 + c], oA);
        oB = fmaf(vB, WB[cc * 16 + c], oB);
        oC = fmaf(vC, WC[cc * 16 + c], oC);
        oD = fmaf(vD, WD[cc * 16 + c], oD);
        oE = fmaf(vE, WE[cc * 16 + c], oE);
    }

    // ---- gate: g[j] = sigmoid(sum_c s[c] * Wg[c][j]); s[c] = oA in half0 lane c
    float gacc = 0.f;
#pragma unroll
    for (int cc = 0; cc < 16; cc++) {
        float sv = __shfl_sync(FULL, oA, cc);
        gacc = fmaf(sv, sWg[cc * 32 + lane], gacc);
    }
    float g   = 1.f / (1.f + __expf(-gacc));     // g[lane]
    float g16 = __shfl_sync(FULL, g, 16 + c);    // g[16+d] for half0 m=4

    float* xo = xout + (size_t)n * ROWF;
    if (!half) {
        xo[c]        = sspf(oA);     // m=0 scalar path
        xo[16 + c]   = oB * g;       // m=1..3 gated by g[d]
        xo[32 + c]   = oC * g;
        xo[48 + c]   = oD * g;
        xo[64 + c]   = oE * g16;     // m=4 gated by g[16+d]
    } else {
        xo[80 + c]   = oA * g;       // m=5..8 gated by g[16+d] = g[lane]
        xo[96 + c]   = oB * g;
        xo[112 + c]  = oC * g;
        xo[128 + c]  = oD * g;
    }
}

// ---------------------------------------------------------------------------
// Readout: out[n] = ssp(x[n,0,:] @ Wr1) @ wr2   (x from buffer 1)
// ---------------------------------------------------------------------------
__global__ void __launch_bounds__(128)
final_kernel(const float* __restrict__ Wr1, const float* __restrict__ wr2,
             float* __restrict__ out) {
    __shared__ float sW[CC * HH];
    __shared__ float sw2[HH];
    for (int i = threadIdx.x; i < CC * HH; i += blockDim.x) sW[i] = Wr1[i];
    for (int i = threadIdx.x; i < HH; i += blockDim.x) sw2[i] = wr2[i];
    __syncthreads();

    int n = blockIdx.x * blockDim.x + threadIdx.x;
    if (n >= NN) return;
    float v[16];
    const float* xp = g_xbuf + XSZ + (size_t)n * ROWF;
#pragma unroll
    for (int c = 0; c < 16; c++) v[c] = xp[c];
    float acc = 0.f;
#pragma unroll
    for (int j = 0; j < HH; j++) {
        float h = 0.f;
#pragma unroll
        for (int c = 0; c < 16; c++) h += v[c] * sW[c * HH + j];
        acc += sspf(h) * sw2[j];
    }
    out[n] = acc;
}

// ---------------------------------------------------------------------------
extern "C" void kernel_launch(void* const* d_in, const int* in_sizes, int n_in,
                              void* d_out, int out_size) {
    const int*   species = (const int*)d_in[0];
    const int*   eidx    = (const int*)d_in[1];
    const float* diff    = (const float*)d_in[2];
    const float* dist    = (const float*)d_in[3];
    const float* Wemb    = (const float*)d_in[4];
    const float* W1      = (const float*)d_in[5];
    const float* W2      = (const float*)d_in[6];
    const float* Wmix    = (const float*)d_in[7];
    const float* Wg      = (const float*)d_in[8];
    const float* Wr1     = (const float*)d_in[9];
    const float* wr2     = (const float*)d_in[10];
    float* out = (float*)d_out;

    build_tables<<<(NL * TABN + 127) / 128, 128>>>(W1, W2);
    zero_cnt<<<(NN + 255) / 256, 256>>>();
    init_x<<<(XSZ + 255) / 256, 256>>>(species, Wemb);
    build_edges<<<(EE + 255) / 256, 256>>>(eidx, diff, dist);
    // layer 0: read buf0 write buf1; layer 1: 1->0; layer 2: 0->1
    layer_kernel<<<(NN + 7) / 8, 256>>>(0, 0, Wmix, Wg);
    layer_kernel<<<(NN + 7) / 8, 256>>>(1, 1, Wmix, Wg);
    layer_kernel<<<(NN + 7) / 8, 256>>>(2, 0, Wmix, Wg);
    final_kernel<<<(NN + 127) / 128, 128>>>(Wr1, wr2, out);
}

// round 4
// speedup vs baseline: 5.1667x; 1.3344x over previous
#include <cuda_runtime.h>

#define NN 20000
#define EE 400000
#define CC 16
#define NSH 9
#define HH 64
#define NB 8
#define NL 3
#define TABN 4096
#define SLOTS 64
#define RMIN 0.5f
#define RCUT 5.0f
#define ROWF (CC*NSH)          // 144 floats per node
#define XSZ (NN*ROWF)

__device__ float  g_xbuf[2 * XSZ];
__device__ float  g_Rtab[NL * TABN * 32];
__device__ float  g_Rsum[TABN * 16];               // layer-2: R1+R2
__device__ int    g_cnt[NN];
__device__ float4 g_rec[(size_t)NN * SLOTS * 3];   // 48B per edge record

__device__ __forceinline__ float sspf(float v) {
    return fmaxf(v, 0.f) + log1pf(__expf(-fabsf(v))) - 0.69314718055994531f;
}

// ---------------------------------------------------------------------------
// Radial tables: R(r) = ssp(ebasis(r) @ W1) @ W2 * deg_norm, 32 values/knot.
// For layer 2 also emit Rsum = R1 + R2 (only combination layer 2 needs).
// ---------------------------------------------------------------------------
__global__ void build_tables(const float* __restrict__ W1,
                             const float* __restrict__ W2) {
    int idx = blockIdx.x * blockDim.x + threadIdx.x;
    if (idx >= NL * TABN) return;
    int layer = idx / TABN;
    int k     = idx % TABN;
    float r = RMIN + (RCUT - RMIN) * ((float)k / (float)(TABN - 1));
    float u = r / RCUT;
    float u3 = u * u * u;
    float u6 = u3 * u3;
    float env = 1.f - 28.f * u6 + 48.f * u6 * u - 21.f * u6 * u * u;
    if (k == TABN - 1) env = 0.f;
    float pref = sqrtf(2.f / RCUT) / r * env;
    float eb[NB];
#pragma unroll
    for (int n = 0; n < NB; n++)
        eb[n] = pref * sinf((float)(n + 1) * 3.14159265358979323846f * r / RCUT);

    const float* w1 = W1 + (size_t)layer * NB * HH;
    const float* w2 = W2 + (size_t)layer * HH * (2 * CC);
    float Racc[32];
#pragma unroll
    for (int c = 0; c < 32; c++) Racc[c] = 0.f;
    for (int j = 0; j < HH; j++) {
        float h = 0.f;
#pragma unroll
        for (int n = 0; n < NB; n++) h += eb[n] * w1[n * HH + j];
        float a = sspf(h);
#pragma unroll
        for (int c = 0; c < 32; c++) Racc[c] += a * w2[j * 32 + c];
    }
    const float deg_norm = 0.22360679774997896f;  // 1/sqrt(20)
    float* dst = g_Rtab + ((size_t)layer * TABN + k) * 32;
#pragma unroll
    for (int c = 0; c < 32; c++) dst[c] = Racc[c] * deg_norm;
    if (layer == 2) {
        float* ds = g_Rsum + (size_t)k * 16;
#pragma unroll
        for (int c = 0; c < 16; c++)
            ds[c] = (Racc[c] + Racc[16 + c]) * deg_norm;
    }
}

// ---------------------------------------------------------------------------
__global__ void zero_cnt() {
    int i = blockIdx.x * blockDim.x + threadIdx.x;
    if (i < NN) g_cnt[i] = 0;
}

// x buffer 0: m=0 row = W_embed[species], rest 0 (only m=0 is ever read by L0)
__global__ void init_x(const int* __restrict__ species,
                       const float* __restrict__ Wemb) {
    int idx = blockIdx.x * blockDim.x + threadIdx.x;
    if (idx >= NN * CC) return;
    int n = idx / CC, c = idx % CC;
    g_xbuf[(size_t)n * ROWF + c] = Wemb[species[n] * CC + c];
}

// ---------------------------------------------------------------------------
// Build slotted CSR: per-edge record {src, t, Y1..Y8} at dst's next slot.
// ---------------------------------------------------------------------------
__global__ void __launch_bounds__(256)
build_edges(const int* __restrict__ eidx, const float* __restrict__ diff,
            const float* __restrict__ dist) {
    int e = blockIdx.x * blockDim.x + threadIdx.x;
    if (e >= EE) return;
    float r = dist[e];
    if (!(r < RCUT)) return;
    int src = eidx[2 * e];
    int dst = eidx[2 * e + 1];
    int pos = atomicAdd(&g_cnt[dst], 1);
    if (pos >= SLOTS) return;   // statistically unreachable

    float dx = diff[3 * e], dy = diff[3 * e + 1], dz = diff[3 * e + 2];
    float inv = rsqrtf(dx * dx + dy * dy + dz * dz);
    float ux = dx * inv, uy = dy * inv, uz = dz * inv;
    const float s3 = 1.7320508075688772f;
    const float s5 = 2.2360679774997896f;
    const float s15 = 3.8729833462074170f;
    float Y1 = s3 * ux, Y2 = s3 * uy, Y3 = s3 * uz;
    float Y4 = s15 * ux * uy;
    float Y5 = s15 * uy * uz;
    float Y6 = 0.5f * s5 * (2.f * uz * uz - ux * ux - uy * uy);
    float Y7 = s15 * ux * uz;
    float Y8 = 0.5f * s15 * (ux * ux - uy * uy);

    float t = (r - RMIN) * ((float)(TABN - 1) / (RCUT - RMIN));
    t = fminf(fmaxf(t, 0.f), (float)(TABN - 1) - 1e-3f);

    float4* rec = g_rec + ((size_t)dst * SLOTS + pos) * 3;
    rec[0] = make_float4(__int_as_float(src), t, Y1, Y2);
    rec[1] = make_float4(Y3, Y4, Y5, Y6);
    rec[2] = make_float4(Y7, Y8, 0.f, 0.f);
}

// ---------------------------------------------------------------------------
// Layer 0 (specialized): input x has only m=0 nonzero. Per edge only x0 row
// (64B) is gathered. Full mix/gate/write of the new x row to buf1.
// Lane layout: half0 (lanes 0-15): m=0..4 at c=lane; half1: m=5..8 at c=lane-16.
// ---------------------------------------------------------------------------
__global__ void __launch_bounds__(256)
layer0_kernel(const float* __restrict__ Wmix, const float* __restrict__ Wg) {
    __shared__ float sWm[3 * CC * CC];
    __shared__ float sWg[CC * 2 * CC];
    for (int i = threadIdx.x; i < 768; i += 256) sWm[i] = Wmix[i];
    for (int i = threadIdx.x; i < 512; i += 256) sWg[i] = Wg[i];
    __syncthreads();

    int n = blockIdx.x * 8 + (threadIdx.x >> 5);
    if (n >= NN) return;
    int lane = threadIdx.x & 31;
    int half = lane >> 4;
    int c    = lane & 15;
    const unsigned FULL = 0xffffffffu;

    const float* xin  = g_xbuf;          // buf0
    float*       xout = g_xbuf + XSZ;    // buf1
    const float* tab  = g_Rtab;          // layer 0

    int cnt = min(g_cnt[n], SLOTS);
    const float4* recbase = g_rec + (size_t)n * SLOTS * 3;

    float a0 = 0.f, a1 = 0.f, a2 = 0.f, a3 = 0.f, a4 = 0.f;

#pragma unroll 2
    for (int e = 0; e < cnt; e++) {
        float4 r0 = recbase[e * 3];
        float4 r1 = recbase[e * 3 + 1];
        float4 r2 = recbase[e * 3 + 2];
        int   src = __float_as_int(r0.x);
        float t   = r0.y;
        int   k0  = (int)t;
        float f   = t - (float)k0;
        const float* T0 = tab + k0 * 32;
        float R1 = fmaf(f, T0[32 + c] - T0[c],       T0[c]);
        float R2 = fmaf(f, T0[48 + c] - T0[16 + c],  T0[16 + c]);

        float x0l = xin[(size_t)src * ROWF + c];   // x[src][0][c]
        float p = R1 * x0l;
        float xa = half ? 0.f : x0l;               // m=0 row only

        float Ya = half ? r1.z : 1.f;    // m=5 : m=0
        float Yb = half ? r1.w : r0.z;   // m=6 : m=1
        float Yc = half ? r2.x : r0.w;   // m=7 : m=2
        float Yd = half ? r2.y : r1.x;   // m=8 : m=3

        a0 = fmaf(p, Ya, fmaf(R2, xa, a0));
        a1 = fmaf(p, Yb, a1);
        a2 = fmaf(p, Yc, a2);
        a3 = fmaf(p, Yd, a3);
        if (!half) a4 = fmaf(p, r1.y, a4);  // m=4
    }

    // ---- mix
    const float* WA = half ? sWm + 512 : sWm;
    const float* WB = half ? sWm + 512 : sWm + 256;
    const float* WC = half ? sWm + 512 : sWm + 256;
    const float* WD = half ? sWm + 512 : sWm + 256;
    const float* WE = sWm + 512;
    int sbase = half << 4;
    float oA = 0.f, oB = 0.f, oC = 0.f, oD = 0.f, oE = 0.f;
#pragma unroll
    for (int cc = 0; cc < 16; cc++) {
        float vA = __shfl_sync(FULL, a0, sbase + cc);
        float vB = __shfl_sync(FULL, a1, sbase + cc);
        float vC = __shfl_sync(FULL, a2, sbase + cc);
        float vD = __shfl_sync(FULL, a3, sbase + cc);
        float vE = __shfl_sync(FULL, a4, sbase + cc);
        oA = fmaf(vA, WA[cc * 16 + c], oA);
        oB = fmaf(vB, WB[cc * 16 + c], oB);
        oC = fmaf(vC, WC[cc * 16 + c], oC);
        oD = fmaf(vD, WD[cc * 16 + c], oD);
        oE = fmaf(vE, WE[cc * 16 + c], oE);
    }

    // ---- gate
    float gacc = 0.f;
#pragma unroll
    for (int cc = 0; cc < 16; cc++) {
        float sv = __shfl_sync(FULL, oA, cc);
        gacc = fmaf(sv, sWg[cc * 32 + lane], gacc);
    }
    float g   = 1.f / (1.f + __expf(-gacc));
    float g16 = __shfl_sync(FULL, g, 16 + c);

    float* xo = xout + (size_t)n * ROWF;
    if (!half) {
        xo[c]       = sspf(oA);
        xo[16 + c]  = oB * g;
        xo[32 + c]  = oC * g;
        xo[48 + c]  = oD * g;
        xo[64 + c]  = oE * g16;
    } else {
        xo[80 + c]  = oA * g;
        xo[96 + c]  = oB * g;
        xo[112 + c] = oC * g;
        xo[128 + c] = oD * g;
    }
}

// ---------------------------------------------------------------------------
// Layer 1 (full): buf1 -> buf0.
// ---------------------------------------------------------------------------
__global__ void __launch_bounds__(256)
layer1_kernel(const float* __restrict__ Wmix, const float* __restrict__ Wg) {
    __shared__ float sWm[3 * CC * CC];
    __shared__ float sWg[CC * 2 * CC];
    for (int i = threadIdx.x; i < 768; i += 256) sWm[i] = Wmix[768 + i];
    for (int i = threadIdx.x; i < 512; i += 256) sWg[i] = Wg[512 + i];
    __syncthreads();

    int n = blockIdx.x * 8 + (threadIdx.x >> 5);
    if (n >= NN) return;
    int lane = threadIdx.x & 31;
    int half = lane >> 4;
    int c    = lane & 15;
    const unsigned FULL = 0xffffffffu;

    const float* xin  = g_xbuf + XSZ;   // buf1
    float*       xout = g_xbuf;         // buf0
    const float* tab  = g_Rtab + (size_t)TABN * 32;  // layer 1

    int cnt = min(g_cnt[n], SLOTS);
    const float4* recbase = g_rec + (size_t)n * SLOTS * 3;
    int xoff = half * 80 + c;

    float a0 = 0.f, a1 = 0.f, a2 = 0.f, a3 = 0.f, a4 = 0.f;

#pragma unroll 2
    for (int e = 0; e < cnt; e++) {
        float4 r0 = recbase[e * 3];
        float4 r1 = recbase[e * 3 + 1];
        float4 r2 = recbase[e * 3 + 2];
        int   src = __float_as_int(r0.x);
        float t   = r0.y;
        int   k0  = (int)t;
        float f   = t - (float)k0;
        const float* T0 = tab + k0 * 32;
        float R1 = fmaf(f, T0[32 + c] - T0[c],       T0[c]);
        float R2 = fmaf(f, T0[48 + c] - T0[16 + c],  T0[16 + c]);

        const float* xb = xin + (size_t)src * ROWF;
        float xa  = xb[xoff];
        float xv1 = xb[xoff + 16];
        float xv2 = xb[xoff + 32];
        float xv3 = xb[xoff + 48];
        float xv4 = xb[c + 64];
        float x0 = __shfl_sync(FULL, xa, c);

        float Ya = half ? r1.z : 1.f;
        float Yb = half ? r1.w : r0.z;
        float Yc = half ? r2.x : r0.w;
        float Yd = half ? r2.y : r1.x;

        float p = R1 * x0;
        a0 = fmaf(p, Ya, fmaf(R2, xa,  a0));
        a1 = fmaf(p, Yb, fmaf(R2, xv1, a1));
        a2 = fmaf(p, Yc, fmaf(R2, xv2, a2));
        a3 = fmaf(p, Yd, fmaf(R2, xv3, a3));
        if (!half) a4 = fmaf(p, r1.y, fmaf(R2, xv4, a4));
    }

    const float* WA = half ? sWm + 512 : sWm;
    const float* WB = half ? sWm + 512 : sWm + 256;
    const float* WC = half ? sWm + 512 : sWm + 256;
    const float* WD = half ? sWm + 512 : sWm + 256;
    const float* WE = sWm + 512;
    int sbase = half << 4;
    float oA = 0.f, oB = 0.f, oC = 0.f, oD = 0.f, oE = 0.f;
#pragma unroll
    for (int cc = 0; cc < 16; cc++) {
        float vA = __shfl_sync(FULL, a0, sbase + cc);
        float vB = __shfl_sync(FULL, a1, sbase + cc);
        float vC = __shfl_sync(FULL, a2, sbase + cc);
        float vD = __shfl_sync(FULL, a3, sbase + cc);
        float vE = __shfl_sync(FULL, a4, sbase + cc);
        oA = fmaf(vA, WA[cc * 16 + c], oA);
        oB = fmaf(vB, WB[cc * 16 + c], oB);
        oC = fmaf(vC, WC[cc * 16 + c], oC);
        oD = fmaf(vD, WD[cc * 16 + c], oD);
        oE = fmaf(vE, WE[cc * 16 + c], oE);
    }

    float gacc = 0.f;
#pragma unroll
    for (int cc = 0; cc < 16; cc++) {
        float sv = __shfl_sync(FULL, oA, cc);
        gacc = fmaf(sv, sWg[cc * 32 + lane], gacc);
    }
    float g   = 1.f / (1.f + __expf(-gacc));
    float g16 = __shfl_sync(FULL, g, 16 + c);

    float* xo = xout + (size_t)n * ROWF;
    if (!half) {
        xo[c]       = sspf(oA);
        xo[16 + c]  = oB * g;
        xo[32 + c]  = oC * g;
        xo[48 + c]  = oD * g;
        xo[64 + c]  = oE * g16;
    } else {
        xo[80 + c]  = oA * g;
        xo[96 + c]  = oB * g;
        xo[112 + c] = oC * g;
        xo[128 + c] = oD * g;
    }
}

// ---------------------------------------------------------------------------
// Layer 2 fused with readout: only the scalar channel survives to the output.
// agg0[c] = sum_e (R1+R2)[c] * x[src][0][c];  s = agg0 @ Wmix[2,0];
// out[n] = ssp(ssp(s) @ Wr1) @ wr2.
// ---------------------------------------------------------------------------
__global__ void __launch_bounds__(256)
layer2_kernel(const float* __restrict__ Wmix, const float* __restrict__ Wr1,
              const float* __restrict__ wr2, float* __restrict__ out) {
    __shared__ float sWm0[CC * CC];   // Wmix[2,0]
    __shared__ float sWr1[CC * HH];
    __shared__ float sw2[HH];
    for (int i = threadIdx.x; i < 256; i += 256) sWm0[i] = Wmix[2 * 768 + i];
    for (int i = threadIdx.x; i < CC * HH; i += 256) sWr1[i] = Wr1[i];
    if (threadIdx.x < HH) sw2[threadIdx.x] = wr2[threadIdx.x];
    __syncthreads();

    int n = blockIdx.x * 8 + (threadIdx.x >> 5);
    if (n >= NN) return;
    int lane = threadIdx.x & 31;
    int c    = lane & 15;
    const unsigned FULL = 0xffffffffu;

    const float* xin = g_xbuf;   // buf0

    int cnt = min(g_cnt[n], SLOTS);
    const float4* recbase = g_rec + (size_t)n * SLOTS * 3;

    float a0 = 0.f;
#pragma unroll 2
    for (int e = 0; e < cnt; e++) {
        float4 r0 = recbase[e * 3];    // only src + t needed
        int   src = __float_as_int(r0.x);
        float t   = r0.y;
        int   k0  = (int)t;
        float f   = t - (float)k0;
        const float* T0 = g_Rsum + k0 * 16;
        float w = fmaf(f, T0[16 + c] - T0[c], T0[c]);
        float x0l = xin[(size_t)src * ROWF + c];
        a0 = fmaf(w, x0l, a0);
    }
    // both halves hold identical a0 (same c); gather from lanes 0..15
    float s = 0.f;
#pragma unroll
    for (int cc = 0; cc < 16; cc++) {
        float v = __shfl_sync(FULL, a0, cc);
        s = fmaf(v, sWm0[cc * 16 + c], s);
    }
    float xs = sspf(s);   // x[n][c][0], duplicated across halves

    // readout: each lane handles j = lane and j = lane + 32
    float h0 = 0.f, h1 = 0.f;
#pragma unroll
    for (int cc = 0; cc < 16; cc++) {
        float v = __shfl_sync(FULL, xs, cc);
        h0 = fmaf(v, sWr1[cc * HH + lane],      h0);
        h1 = fmaf(v, sWr1[cc * HH + lane + 32], h1);
    }
    float part = sspf(h0) * sw2[lane] + sspf(h1) * sw2[lane + 32];
#pragma unroll
    for (int off = 16; off > 0; off >>= 1)
        part += __shfl_xor_sync(FULL, part, off);
    if (lane == 0) out[n] = part;
}

// ---------------------------------------------------------------------------
extern "C" void kernel_launch(void* const* d_in, const int* in_sizes, int n_in,
                              void* d_out, int out_size) {
    const int*   species = (const int*)d_in[0];
    const int*   eidx    = (const int*)d_in[1];
    const float* diff    = (const float*)d_in[2];
    const float* dist    = (const float*)d_in[3];
    const float* Wemb    = (const float*)d_in[4];
    const float* W1      = (const float*)d_in[5];
    const float* W2      = (const float*)d_in[6];
    const float* Wmix    = (const float*)d_in[7];
    const float* Wg      = (const float*)d_in[8];
    const float* Wr1     = (const float*)d_in[9];
    const float* wr2     = (const float*)d_in[10];
    float* out = (float*)d_out;

    build_tables<<<(NL * TABN + 127) / 128, 128>>>(W1, W2);
    zero_cnt<<<(NN + 255) / 256, 256>>>();
    init_x<<<(NN * CC + 255) / 256, 256>>>(species, Wemb);
    build_edges<<<(EE + 255) / 256, 256>>>(eidx, diff, dist);
    layer0_kernel<<<(NN + 7) / 8, 256>>>(Wmix, Wg);
    layer1_kernel<<<(NN + 7) / 8, 256>>>(Wmix, Wg);
    layer2_kernel<<<(NN + 7) / 8, 256>>>(Wmix, Wr1, wr2, out);
}

// round 5
// speedup vs baseline: 14.2735x; 2.7626x over previous
#include <cuda_runtime.h>

#define NN 20000
#define EE 400000
#define CC 16
#define HH 64
#define NB 8
#define NL 3
#define TABN 4096
#define SLOTS 64
#define RMIN 0.5f
#define RCUT 5.0f

__device__ float  g_xs[2 * NN * CC];             // scalar channel, double buffered
__device__ float2 g_Rpair[NL * TABN * CC];       // (Rsum[k][c], Rsum[k+1][c])
__device__ int    g_cnt[NN];
__device__ float2 g_rec[(size_t)NN * SLOTS];     // {src, t} per edge

__device__ __forceinline__ float sspf(float v) {
    return fmaxf(v, 0.f) + log1pf(__expf(-fabsf(v))) - 0.69314718055994531f;
}

// ---------------------------------------------------------------------------
// Radial tables, warp per (layer, knot):
//   Rsum[c] = deg_norm * sum_j ssp(ebasis(r)@W1)[j] * (W2[j][c] + W2[j][16+c])
// Stored as adjacent-knot float2 pairs for single-load lerp.
// Also zeroes g_cnt (first NN threads).
// ---------------------------------------------------------------------------
__global__ void __launch_bounds__(256)
build_tables(const float* __restrict__ W1, const float* __restrict__ W2) {
    int gtid = blockIdx.x * 256 + threadIdx.x;
    if (gtid < NN) g_cnt[gtid] = 0;

    int gw   = gtid >> 5;
    int lane = threadIdx.x & 31;
    if (gw >= NL * TABN) return;
    int layer = gw / TABN;
    int k     = gw % TABN;

    __shared__ float sa[8][64];
    float* a = sa[(threadIdx.x >> 5)];

    float r = RMIN + (RCUT - RMIN) * ((float)k / (float)(TABN - 1));
    float u = r / RCUT;
    float u3 = u * u * u;
    float u6 = u3 * u3;
    float env = 1.f - 28.f * u6 + 48.f * u6 * u - 21.f * u6 * u * u;
    if (k == TABN - 1) env = 0.f;
    float pref = sqrtf(2.f / RCUT) / r * env;
    float eb[NB];
#pragma unroll
    for (int n = 0; n < NB; n++)
        eb[n] = pref * sinf((float)(n + 1) * 3.14159265358979323846f * r / RCUT);

    const float* w1 = W1 + (size_t)layer * NB * HH;
    const float* w2 = W2 + (size_t)layer * HH * (2 * CC);
#pragma unroll
    for (int rep = 0; rep < 2; rep++) {
        int j = lane + rep * 32;
        float h = 0.f;
#pragma unroll
        for (int n = 0; n < NB; n++) h = fmaf(eb[n], w1[n * HH + j], h);
        a[j] = sspf(h);
    }
    __syncwarp();

    if (lane < CC) {
        float acc = 0.f;
#pragma unroll
        for (int j = 0; j < HH; j++)
            acc = fmaf(a[j], w2[j * 32 + lane] + w2[j * 32 + 16 + lane], acc);
        float val = acc * 0.22360679774997896f;   // deg_norm = 1/sqrt(20)
        float2* base = g_Rpair + (size_t)layer * TABN * CC;
        base[k * CC + lane].x = val;
        if (k > 0) base[(k - 1) * CC + lane].y = val;
    }
}

// ---------------------------------------------------------------------------
// Build slotted CSR records {src, t}; also initialize xs buffer 0 from the
// species embedding (first NN*CC threads).
// ---------------------------------------------------------------------------
__global__ void __launch_bounds__(256)
build_edges(const int* __restrict__ eidx, const float* __restrict__ dist,
            const int* __restrict__ species, const float* __restrict__ Wemb) {
    int tid = blockIdx.x * 256 + threadIdx.x;
    if (tid < NN * CC) {
        int n = tid >> 4, c = tid & 15;
        g_xs[n * CC + c] = Wemb[species[n] * CC + c];
    }
    if (tid >= EE) return;
    float r = dist[tid];
    if (!(r < RCUT)) return;
    int src = eidx[2 * tid];
    int dst = eidx[2 * tid + 1];
    int pos = atomicAdd(&g_cnt[dst], 1);
    if (pos >= SLOTS) return;   // statistically unreachable (Poisson ~16.4)
    float t = (r - RMIN) * ((float)(TABN - 1) / (RCUT - RMIN));
    t = fminf(fmaxf(t, 0.f), (float)(TABN - 1) - 1e-3f);
    g_rec[(size_t)dst * SLOTS + pos] = make_float2(__int_as_float(src), t);
}

// ---------------------------------------------------------------------------
// Scalar layer: half-warp per node (lane c = channel).
//   agg[c] = sum_e lerp(Rpair[layer], t_e)[c] * xs_in[src_e][c]
//   xs_out[n][c] = ssp( sum_cc agg[cc] * Wmix[layer,0][cc][c] )
// ---------------------------------------------------------------------------
__global__ void __launch_bounds__(256)
layer_kernel(int layer, int rd, const float* __restrict__ Wmix) {
    __shared__ float sW[CC * CC];
    for (int i = threadIdx.x; i < 256; i += 256) sW[i] = Wmix[layer * 768 + i];
    __syncthreads();

    const unsigned FULL = 0xffffffffu;
    int lane = threadIdx.x & 31;
    int half = lane >> 4;
    int c    = lane & 15;
    int n = blockIdx.x * 16 + ((threadIdx.x >> 5) << 1) + half;  // grid covers NN exactly

    const float*  xin  = g_xs + rd * (NN * CC);
    float*        xout = g_xs + (1 - rd) * (NN * CC);
    const float2* tab  = g_Rpair + (size_t)layer * TABN * CC;
    const float2* rec  = g_rec + (size_t)n * SLOTS;
    int cnt = min(g_cnt[n], SLOTS);

    float a0 = 0.f, a1 = 0.f;
    int e = 0;
    for (; e + 2 <= cnt; e += 2) {
        float2 rA = rec[e], rB = rec[e + 1];
        int   sA = __float_as_int(rA.x), sB = __float_as_int(rB.x);
        int   kA = (int)rA.y,            kB = (int)rB.y;
        float fA = rA.y - (float)kA,     fB = rB.y - (float)kB;
        float2 pA = tab[kA * CC + c],    pB = tab[kB * CC + c];
        float wA = fmaf(fA, pA.y - pA.x, pA.x);
        float wB = fmaf(fB, pB.y - pB.x, pB.x);
        a0 = fmaf(wA, xin[sA * CC + c], a0);
        a1 = fmaf(wB, xin[sB * CC + c], a1);
    }
    if (e < cnt) {
        float2 rA = rec[e];
        int   sA = __float_as_int(rA.x);
        int   kA = (int)rA.y;
        float fA = rA.y - (float)kA;
        float2 pA = tab[kA * CC + c];
        a0 = fmaf(fmaf(fA, pA.y - pA.x, pA.x), xin[sA * CC + c], a0);
    }
    float a = a0 + a1;

    float s = 0.f;
    int base = half << 4;
#pragma unroll
    for (int cc = 0; cc < 16; cc++) {
        float v = __shfl_sync(FULL, a, base + cc);
        s = fmaf(v, sW[cc * 16 + c], s);
    }
    xout[n * CC + c] = sspf(s);
}

// ---------------------------------------------------------------------------
// Layer 2 fused with readout: out[n] = ssp(ssp(agg@Wmix[2,0]) @ Wr1) @ wr2
// ---------------------------------------------------------------------------
__global__ void __launch_bounds__(256)
layer2_kernel(const float* __restrict__ Wmix, const float* __restrict__ Wr1,
              const float* __restrict__ wr2, float* __restrict__ out) {
    __shared__ float sW[CC * CC];
    __shared__ float sWr1[CC * HH];
    __shared__ float sw2[HH];
    for (int i = threadIdx.x; i < 256; i += 256) sW[i] = Wmix[2 * 768 + i];
    for (int i = threadIdx.x; i < CC * HH; i += 256) sWr1[i] = Wr1[i];
    if (threadIdx.x < HH) sw2[threadIdx.x] = wr2[threadIdx.x];
    __syncthreads();

    const unsigned FULL = 0xffffffffu;
    int lane = threadIdx.x & 31;
    int half = lane >> 4;
    int c    = lane & 15;
    int n = blockIdx.x * 16 + ((threadIdx.x >> 5) << 1) + half;

    const float*  xin = g_xs;   // buf0 (layer-1 output)
    const float2* tab = g_Rpair + (size_t)2 * TABN * CC;
    const float2* rec = g_rec + (size_t)n * SLOTS;
    int cnt = min(g_cnt[n], SLOTS);

    float a0 = 0.f, a1 = 0.f;
    int e = 0;
    for (; e + 2 <= cnt; e += 2) {
        float2 rA = rec[e], rB = rec[e + 1];
        int   sA = __float_as_int(rA.x), sB = __float_as_int(rB.x);
        int   kA = (int)rA.y,            kB = (int)rB.y;
        float fA = rA.y - (float)kA,     fB = rB.y - (float)kB;
        float2 pA = tab[kA * CC + c],    pB = tab[kB * CC + c];
        float wA = fmaf(fA, pA.y - pA.x, pA.x);
        float wB = fmaf(fB, pB.y - pB.x, pB.x);
        a0 = fmaf(wA, xin[sA * CC + c], a0);
        a1 = fmaf(wB, xin[sB * CC + c], a1);
    }
    if (e < cnt) {
        float2 rA = rec[e];
        int   sA = __float_as_int(rA.x);
        int   kA = (int)rA.y;
        float fA = rA.y - (float)kA;
        float2 pA = tab[kA * CC + c];
        a0 = fmaf(fmaf(fA, pA.y - pA.x, pA.x), xin[sA * CC + c], a0);
    }
    float a = a0 + a1;

    float s = 0.f;
    int base = half << 4;
#pragma unroll
    for (int cc = 0; cc < 16; cc++) {
        float v = __shfl_sync(FULL, a, base + cc);
        s = fmaf(v, sW[cc * 16 + c], s);
    }
    float xsv = sspf(s);

    // readout: lane c handles j = c, c+16, c+32, c+48
    float h0 = 0.f, h1 = 0.f, h2 = 0.f, h3 = 0.f;
#pragma unroll
    for (int cc = 0; cc < 16; cc++) {
        float v = __shfl_sync(FULL, xsv, base + cc);
        h0 = fmaf(v, sWr1[cc * HH + c],      h0);
        h1 = fmaf(v, sWr1[cc * HH + c + 16], h1);
        h2 = fmaf(v, sWr1[cc * HH + c + 32], h2);
        h3 = fmaf(v, sWr1[cc * HH + c + 48], h3);
    }
    float part = sspf(h0) * sw2[c] + sspf(h1) * sw2[c + 16]
               + sspf(h2) * sw2[c + 32] + sspf(h3) * sw2[c + 48];
    part += __shfl_xor_sync(FULL, part, 8);
    part += __shfl_xor_sync(FULL, part, 4);
    part += __shfl_xor_sync(FULL, part, 2);
    part += __shfl_xor_sync(FULL, part, 1);
    if (c == 0) out[n] = part;
}

// ---------------------------------------------------------------------------
extern "C" void kernel_launch(void* const* d_in, const int* in_sizes, int n_in,
                              void* d_out, int out_size) {
    const int*   species = (const int*)d_in[0];
    const int*   eidx    = (const int*)d_in[1];
    const float* dist    = (const float*)d_in[3];
    const float* Wemb    = (const float*)d_in[4];
    const float* W1      = (const float*)d_in[5];
    const float* W2      = (const float*)d_in[6];
    const float* Wmix    = (const float*)d_in[7];
    const float* Wr1     = (const float*)d_in[9];
    const float* wr2     = (const float*)d_in[10];
    float* out = (float*)d_out;

    build_tables<<<(NL * TABN * 32 + 255) / 256, 256>>>(W1, W2);
    build_edges<<<(EE + 255) / 256, 256>>>(eidx, dist, species, Wemb);
    layer_kernel<<<NN / 16, 256>>>(0, 0, Wmix);   // buf0 -> buf1
    layer_kernel<<<NN / 16, 256>>>(1, 1, Wmix);   // buf1 -> buf0
    layer2_kernel<<<NN / 16, 256>>>(Wmix, Wr1, wr2, out);
}

// round 6
// speedup vs baseline: 15.9219x; 1.1155x over previous
#include <cuda_runtime.h>

#define NN 20000
#define EE 400000
#define CC 16
#define HH 64
#define NB 8
#define NL 3
#define TABN 4096
#define SLOTS 64
#define RMIN 0.5f
#define RCUT 5.0f

__device__ float  g_xs[2 * NN * CC];               // scalar channel, double buffered
__device__ float4 g_Rtab4[NL * TABN * 8];          // [layer][knot][q]: {Rk[2q],Rk1[2q],Rk[2q+1],Rk1[2q+1]}
__device__ int    g_cnt[NN];
__device__ float2 g_rec[(size_t)NN * SLOTS];       // {srcoff = src*CC, t}

__device__ __forceinline__ float sspf(float v) {
    // softplus(v) - ln2, fast: |abs err| ~1e-7
    float z = __expf(-fabsf(v));
    return fmaxf(v, 0.f) + __logf(1.f + z) - 0.69314718055994531f;
}

// ---------------------------------------------------------------------------
// Radial tables, warp per (layer, knot):
//   Rsum[c] = deg_norm * sum_j ssp(ebasis(r)@W1)[j] * (W2[j][c] + W2[j][16+c])
// Packed so one float4 load serves the 2-channel lerp.
// Also zeroes g_cnt (first NN threads).
// ---------------------------------------------------------------------------
__global__ void __launch_bounds__(256)
build_tables(const float* __restrict__ W1, const float* __restrict__ W2) {
    int gtid = blockIdx.x * 256 + threadIdx.x;
    if (gtid < NN) g_cnt[gtid] = 0;

    int gw   = gtid >> 5;
    int lane = threadIdx.x & 31;
    if (gw >= NL * TABN) return;
    int layer = gw / TABN;
    int k     = gw % TABN;

    __shared__ float sa[8][64];
    float* a = sa[(threadIdx.x >> 5)];

    float r = RMIN + (RCUT - RMIN) * ((float)k / (float)(TABN - 1));
    float u = r / RCUT;
    float u3 = u * u * u;
    float u6 = u3 * u3;
    float env = 1.f - 28.f * u6 + 48.f * u6 * u - 21.f * u6 * u * u;
    if (k == TABN - 1) env = 0.f;
    float pref = sqrtf(2.f / RCUT) / r * env;
    float eb[NB];
#pragma unroll
    for (int n = 0; n < NB; n++)
        eb[n] = pref * sinf((float)(n + 1) * 3.14159265358979323846f * r / RCUT);

    const float* w1 = W1 + (size_t)layer * NB * HH;
    const float* w2 = W2 + (size_t)layer * HH * (2 * CC);
#pragma unroll
    for (int rep = 0; rep < 2; rep++) {
        int j = lane + rep * 32;
        float h = 0.f;
#pragma unroll
        for (int n = 0; n < NB; n++) h = fmaf(eb[n], w1[n * HH + j], h);
        a[j] = sspf(h);
    }
    __syncwarp();

    if (lane < CC) {
        int c = lane;
        float acc = 0.f;
#pragma unroll
        for (int j = 0; j < HH; j++)
            acc = fmaf(a[j], w2[j * 32 + c] + w2[j * 32 + 16 + c], acc);
        float val = acc * 0.22360679774997896f;   // deg_norm = 1/sqrt(20)
        // scatter into packed layout
        float* T = (float*)(g_Rtab4 + ((size_t)layer * TABN) * 8);
        int q = c >> 1, pos = (c & 1) * 2;
        T[(k * 8 + q) * 4 + pos] = val;                       // Rk[c] slot
        if (k > 0) T[((k - 1) * 8 + q) * 4 + pos + 1] = val;  // Rk-1's "next" slot
    }
}

// ---------------------------------------------------------------------------
// Build slotted CSR records {srcoff, t}; also init xs buffer 0 from embedding.
// ---------------------------------------------------------------------------
__global__ void __launch_bounds__(256)
build_edges(const int* __restrict__ eidx, const float* __restrict__ dist,
            const int* __restrict__ species, const float* __restrict__ Wemb) {
    int tid = blockIdx.x * 256 + threadIdx.x;
    if (tid < NN * CC) {
        int n = tid >> 4, c = tid & 15;
        g_xs[n * CC + c] = Wemb[species[n] * CC + c];
    }
    if (tid >= EE) return;
    float r = dist[tid];
    if (!(r < RCUT)) return;
    int src = eidx[2 * tid];
    int dst = eidx[2 * tid + 1];
    int pos = atomicAdd(&g_cnt[dst], 1);
    if (pos >= SLOTS) return;   // statistically unreachable (Poisson ~16.4)
    float t = (r - RMIN) * ((float)(TABN - 1) / (RCUT - RMIN));
    t = fminf(fmaxf(t, 0.f), (float)(TABN - 1) - 1e-3f);
    g_rec[(size_t)dst * SLOTS + pos] = make_float2(__int_as_float(src * CC), t);
}

// ---------------------------------------------------------------------------
// Scalar layer, VEC=2: warp = 4 nodes, 8 lanes/node, 2 channels/lane.
//   agg[c] = sum_e w_e[c] * xs_in[src_e][c];  xs_out = ssp(agg @ Wmix[l,0])
// ---------------------------------------------------------------------------
__global__ void __launch_bounds__(256)
layer_kernel(int layer, int rd, const float* __restrict__ Wmix) {
    __shared__ float sW[CC * CC];
    for (int i = threadIdx.x; i < 256; i += 256) sW[i] = Wmix[layer * 768 + i];
    __syncthreads();

    const unsigned FULL = 0xffffffffu;
    int lane = threadIdx.x & 31;
    int q    = lane & 7;                       // channel pair index
    int n = blockIdx.x * 32 + ((threadIdx.x >> 5) << 2) + (lane >> 3);

    const float*  xin  = g_xs + rd * (NN * CC);
    float*        xout = g_xs + (1 - rd) * (NN * CC);
    const float4* tab  = g_Rtab4 + (size_t)layer * TABN * 8;
    const float2* rec  = g_rec + (size_t)n * SLOTS;
    int cnt = min(g_cnt[n], SLOTS);

    float a0 = 0.f, a1 = 0.f, b0 = 0.f, b1 = 0.f;
    int e = 0;
    for (; e + 2 <= cnt; e += 2) {
        float2 rA = rec[e], rB = rec[e + 1];
        int   sA = __float_as_int(rA.x), sB = __float_as_int(rB.x);
        int   kA = (int)rA.y,            kB = (int)rB.y;
        float fA = rA.y - (float)kA,     fB = rB.y - (float)kB;
        float4 pA = tab[kA * 8 + q],     pB = tab[kB * 8 + q];
        const float2 xA = *(const float2*)(xin + sA + 2 * q);
        const float2 xB = *(const float2*)(xin + sB + 2 * q);
        float wA0 = fmaf(fA, pA.y - pA.x, pA.x);
        float wA1 = fmaf(fA, pA.w - pA.z, pA.z);
        float wB0 = fmaf(fB, pB.y - pB.x, pB.x);
        float wB1 = fmaf(fB, pB.w - pB.z, pB.z);
        a0 = fmaf(wA0, xA.x, a0);
        a1 = fmaf(wA1, xA.y, a1);
        b0 = fmaf(wB0, xB.x, b0);
        b1 = fmaf(wB1, xB.y, b1);
    }
    if (e < cnt) {
        float2 rA = rec[e];
        int   sA = __float_as_int(rA.x);
        int   kA = (int)rA.y;
        float fA = rA.y - (float)kA;
        float4 pA = tab[kA * 8 + q];
        const float2 xA = *(const float2*)(xin + sA + 2 * q);
        a0 = fmaf(fmaf(fA, pA.y - pA.x, pA.x), xA.x, a0);
        a1 = fmaf(fmaf(fA, pA.w - pA.z, pA.z), xA.y, a1);
    }
    float acc0 = a0 + b0;   // agg[2q]
    float acc1 = a1 + b1;   // agg[2q+1]

    // mix: s[d] = sum_cc agg[cc] * W[cc][d], d = 2q, 2q+1
    int gbase = lane & 24;   // first lane of this node's 8-lane group
    float s0 = 0.f, s1 = 0.f;
#pragma unroll
    for (int cc = 0; cc < 16; cc++) {
        float v = __shfl_sync(FULL, (cc & 1) ? acc1 : acc0, gbase + (cc >> 1));
        s0 = fmaf(v, sW[cc * 16 + 2 * q],     s0);
        s1 = fmaf(v, sW[cc * 16 + 2 * q + 1], s1);
    }
    float2 o = make_float2(sspf(s0), sspf(s1));
    *(float2*)(xout + n * CC + 2 * q) = o;
}

// ---------------------------------------------------------------------------
// Layer 2 fused with readout: out[n] = ssp(ssp(agg@Wmix[2,0]) @ Wr1) @ wr2
// ---------------------------------------------------------------------------
__global__ void __launch_bounds__(256)
layer2_kernel(const float* __restrict__ Wmix, const float* __restrict__ Wr1,
              const float* __restrict__ wr2, float* __restrict__ out) {
    __shared__ float sW[CC * CC];
    __shared__ float sWr1[CC * HH];
    __shared__ float sw2[HH];
    for (int i = threadIdx.x; i < 256; i += 256) sW[i] = Wmix[2 * 768 + i];
    for (int i = threadIdx.x; i < CC * HH; i += 256) sWr1[i] = Wr1[i];
    if (threadIdx.x < HH) sw2[threadIdx.x] = wr2[threadIdx.x];
    __syncthreads();

    const unsigned FULL = 0xffffffffu;
    int lane = threadIdx.x & 31;
    int q    = lane & 7;
    int n = blockIdx.x * 32 + ((threadIdx.x >> 5) << 2) + (lane >> 3);

    const float*  xin = g_xs;   // buf0 (layer-1 output)
    const float4* tab = g_Rtab4 + (size_t)2 * TABN * 8;
    const float2* rec = g_rec + (size_t)n * SLOTS;
    int cnt = min(g_cnt[n], SLOTS);

    float a0 = 0.f, a1 = 0.f, b0 = 0.f, b1 = 0.f;
    int e = 0;
    for (; e + 2 <= cnt; e += 2) {
        float2 rA = rec[e], rB = rec[e + 1];
        int   sA = __float_as_int(rA.x), sB = __float_as_int(rB.x);
        int   kA = (int)rA.y,            kB = (int)rB.y;
        float fA = rA.y - (float)kA,     fB = rB.y - (float)kB;
        float4 pA = tab[kA * 8 + q],     pB = tab[kB * 8 + q];
        const float2 xA = *(const float2*)(xin + sA + 2 * q);
        const float2 xB = *(const float2*)(xin + sB + 2 * q);
        a0 = fmaf(fmaf(fA, pA.y - pA.x, pA.x), xA.x, a0);
        a1 = fmaf(fmaf(fA, pA.w - pA.z, pA.z), xA.y, a1);
        b0 = fmaf(fmaf(fB, pB.y - pB.x, pB.x), xB.x, b0);
        b1 = fmaf(fmaf(fB, pB.w - pB.z, pB.z), xB.y, b1);
    }
    if (e < cnt) {
        float2 rA = rec[e];
        int   sA = __float_as_int(rA.x);
        int   kA = (int)rA.y;
        float fA = rA.y - (float)kA;
        float4 pA = tab[kA * 8 + q];
        const float2 xA = *(const float2*)(xin + sA + 2 * q);
        a0 = fmaf(fmaf(fA, pA.y - pA.x, pA.x), xA.x, a0);
        a1 = fmaf(fmaf(fA, pA.w - pA.z, pA.z), xA.y, a1);
    }
    float acc0 = a0 + b0;
    float acc1 = a1 + b1;

    int gbase = lane & 24;
    float s0 = 0.f, s1 = 0.f;
#pragma unroll
    for (int cc = 0; cc < 16; cc++) {
        float v = __shfl_sync(FULL, (cc & 1) ? acc1 : acc0, gbase + (cc >> 1));
        s0 = fmaf(v, sW[cc * 16 + 2 * q],     s0);
        s1 = fmaf(v, sW[cc * 16 + 2 * q + 1], s1);
    }
    float x0 = sspf(s0);   // x[n][2q][0]
    float x1 = sspf(s1);   // x[n][2q+1][0]

    // readout: lane q handles j = 8q .. 8q+7
    float h[8];
#pragma unroll
    for (int jj = 0; jj < 8; jj++) h[jj] = 0.f;
#pragma unroll
    for (int cc = 0; cc < 16; cc++) {
        float v = __shfl_sync(FULL, (cc & 1) ? x1 : x0, gbase + (cc >> 1));
        const float* wrow = sWr1 + cc * HH + q * 8;
#pragma unroll
        for (int jj = 0; jj < 8; jj++) h[jj] = fmaf(v, wrow[jj], h[jj]);
    }
    float part = 0.f;
#pragma unroll
    for (int jj = 0; jj < 8; jj++) part += sspf(h[jj]) * sw2[q * 8 + jj];
    part += __shfl_xor_sync(FULL, part, 4);
    part += __shfl_xor_sync(FULL, part, 2);
    part += __shfl_xor_sync(FULL, part, 1);
    if (q == 0) out[n] = part;
}

// ---------------------------------------------------------------------------
extern "C" void kernel_launch(void* const* d_in, const int* in_sizes, int n_in,
                              void* d_out, int out_size) {
    const int*   species = (const int*)d_in[0];
    const int*   eidx    = (const int*)d_in[1];
    const float* dist    = (const float*)d_in[3];
    const float* Wemb    = (const float*)d_in[4];
    const float* W1      = (const float*)d_in[5];
    const float* W2      = (const float*)d_in[6];
    const float* Wmix    = (const float*)d_in[7];
    const float* Wr1     = (const float*)d_in[9];
    const float* wr2     = (const float*)d_in[10];
    float* out = (float*)d_out;

    build_tables<<<(NL * TABN * 32 + 255) / 256, 256>>>(W1, W2);
    build_edges<<<(EE + 255) / 256, 256>>>(eidx, dist, species, Wemb);
    layer_kernel<<<NN / 32, 256>>>(0, 0, Wmix);   // buf0 -> buf1
    layer_kernel<<<NN / 32, 256>>>(1, 1, Wmix);   // buf1 -> buf0
    layer2_kernel<<<NN / 32, 256>>>(Wmix, Wr1, wr2, out);
}